// round 9
// baseline (speedup 1.0000x reference)
#include <cuda_runtime.h>
#include <cstdint>

#define ND 729
#define NA 180
#define NB 2
#define NH 512
#define NW 512
#define PI_D 3.141592653589793
#define PI_F 3.14159265358979f

// Scratch (no cudaMalloc allowed)
__device__ float2 g_filt2[NA * ND];    // batch-interleaved: [a][d] -> (b0, b1)
__device__ float2 g_cs[NA];            // (cos*S, sin*S), S = 729/(2*pi)
__device__ float4 g_edge[NA];          // {f0_b0, f728_b0, f0_b1, f728_b1}
__device__ float4 g_pre[NA + 1];       // exclusive prefix of g_edge over a

// ---------------------------------------------------------------------------
// Kernel 1: filter via closed-form piecewise-linear conv kernel
//   h(d) = (1/729)*(1/8 + min(d,729-d)/1458)
// prefix sums P,Q over the single row; doubled-array prefixes reconstructed.
// Also emits g_edge[a] and g_cs.
// ---------------------------------------------------------------------------
__global__ void __launch_bounds__(128) k_filter(const float* __restrict__ sino) {
    __shared__ float  s_sh[768];
    __shared__ float2 pq[730];
    __shared__ float2 wsum[4];

    int tid = threadIdx.x, lane = tid & 31, wid = tid >> 5;
    int row = blockIdx.x;
    int b = (row >= NA) ? 1 : 0;
    int a = row - b * NA;
    const float* src = sino + row * ND;

    for (int i = tid; i < 768; i += 128) s_sh[i] = (i < ND) ? __ldg(src + i) : 0.f;
    __syncthreads();

    int j0 = tid * 6;
    float2 loc[6];
    float p = 0.f, q = 0.f;
    #pragma unroll
    for (int k = 0; k < 6; k++) {
        int j = j0 + k;
        float v = s_sh[j];
        p += v;
        q = fmaf((float)j, v, q);
        loc[k] = make_float2(p, q);
    }
    float tp = p, tq = q;

    #pragma unroll
    for (int o = 1; o < 32; o <<= 1) {
        float ax = __shfl_up_sync(0xffffffffu, p, o);
        float aq = __shfl_up_sync(0xffffffffu, q, o);
        if (lane >= o) { p += ax; q += aq; }
    }
    if (lane == 31) wsum[wid] = make_float2(p, q);
    __syncthreads();

    float wx = 0.f, wq = 0.f;
    #pragma unroll
    for (int w = 0; w < 4; w++)
        if (w < wid) { wx += wsum[w].x; wq += wsum[w].y; }
    float ex = wx + p - tp, eq = wq + q - tq;

    if (tid == 0) pq[0] = make_float2(0.f, 0.f);
    #pragma unroll
    for (int k = 0; k < 6; k++) {
        int j = j0 + k;
        if (j < ND) pq[j + 1] = make_float2(ex + loc[k].x, eq + loc[k].y);
    }
    __syncthreads();

    float T = pq[ND].x, Q9 = pq[ND].y;
    const float c0T = T * (1.0f / 5832.0f);
    const float c1  = 1.0f / 1062882.0f;

    float* fdst = (float*)g_filt2;
    for (int n = tid; n < ND; n += 128) {
        float2 A = pq[n + 1];
        float2 B;
        if (n + 365 <= ND) B = pq[n + 365];
        else { float2 r = pq[n + 365 - ND]; B = make_float2(T + r.x, Q9 + r.y + 729.f * r.x); }
        float2 C;
        { float2 r = pq[n + 1]; C = make_float2(T + r.x, Q9 + r.y + 729.f * r.x); }
        float W = (float)(n + 729) * (C.x - B.x) - (C.y - B.y)
                + (B.y - A.y) - (float)n * (B.x - A.x);
        float f = fmaf(c1, W, c0T);
        fdst[(a * ND + n) * 2 + b] = f;
        if (n == 0)   ((float*)(g_edge + a))[2 * b + 0] = f;
        if (n == 728) ((float*)(g_edge + a))[2 * b + 1] = f;
    }

    if (tid == 0 && b == 0) {
        double ang = (double)a * (PI_D / 179.0);
        double S = 729.0 / (2.0 * PI_D);
        g_cs[a] = make_float2((float)(cos(ang) * S), (float)(sin(ang) * S));
    }
}

// ---------------------------------------------------------------------------
// Kernel 2: tiny — exclusive 4-channel prefix of g_edge into g_pre.
// ---------------------------------------------------------------------------
__global__ void __launch_bounds__(32) k_edge() {
    int lane = threadIdx.x;
    float4 acc = make_float4(0.f, 0.f, 0.f, 0.f);
    float4 loc[6];
    #pragma unroll
    for (int k = 0; k < 6; k++) {
        int a = lane * 6 + k;
        float4 v = (a < NA) ? g_edge[a] : make_float4(0.f, 0.f, 0.f, 0.f);
        acc.x += v.x; acc.y += v.y; acc.z += v.z; acc.w += v.w;
        loc[k] = acc;
    }
    float4 tot = acc;
    #pragma unroll
    for (int o = 1; o < 32; o <<= 1) {
        float ax = __shfl_up_sync(0xffffffffu, acc.x, o);
        float ay = __shfl_up_sync(0xffffffffu, acc.y, o);
        float az = __shfl_up_sync(0xffffffffu, acc.z, o);
        float aw = __shfl_up_sync(0xffffffffu, acc.w, o);
        if (lane >= o) { acc.x += ax; acc.y += ay; acc.z += az; acc.w += aw; }
    }
    float4 excl = make_float4(acc.x - tot.x, acc.y - tot.y, acc.z - tot.z, acc.w - tot.w);
    #pragma unroll
    for (int k = 0; k < 6; k++) {
        int a = lane * 6 + k;
        if (a < NA)
            g_pre[a + 1] = make_float4(excl.x + loc[k].x, excl.y + loc[k].y,
                                       excl.z + loc[k].z, excl.w + loc[k].w);
    }
    if (lane == 0) g_pre[0] = make_float4(0.f, 0.f, 0.f, 0.f);
}

// ---------------------------------------------------------------------------
// Kernel 3: backprojection, warp-uniform window union.
// t(a) = rS*cos(theta_a - phi). Zero angle ts = phi + pi/2 (mod pi).
// All lanes unwrapped into lane0's frame (spread < pi/2 at rS>=1500), then
// warp-reduced union [aL, aH]. One uniform exact loop + branchless per-lane
// clip-sum over the complement via g_pre.
// ---------------------------------------------------------------------------
__device__ __forceinline__ void exact_range(int lo, int hi, float xc, float yc,
                                            const float2* cs, float& e0, float& e1) {
    const float2* f2 = (const float2*)g_filt2;
    #pragma unroll 2
    for (int a = lo; a <= hi; a++) {
        float2 t2 = cs[a];
        float t = fmaf(yc, t2.y, xc * t2.x);
        t = fminf(fmaxf(t, 0.f), 728.f);
        int idx = (int)t;
        float2 v = __ldg(f2 + a * ND + idx);
        e0 += v.x;
        e1 += v.y;
    }
}

// per-lane clip-sum over [lo,hi], sign sampled at (in-complement) index a_s
__device__ __forceinline__ void clip_range(int lo, int hi, int a_s,
                                           float xc, float yc, const float2* cs,
                                           float& e0, float& e1) {
    float2 t2 = cs[a_s];
    float t = fmaf(yc, t2.y, xc * t2.x);
    float4 Hi = __ldg(&g_pre[hi + 1]);
    float4 Lo = __ldg(&g_pre[lo]);
    if (t > 0.f) { e0 += Hi.y - Lo.y; e1 += Hi.w - Lo.w; }
    else         { e0 += Hi.x - Lo.x; e1 += Hi.z - Lo.z; }
}

__global__ void __launch_bounds__(256) k_backproj(float* __restrict__ out) {
    __shared__ float2 cs[NA];
    int tid = threadIdx.x;
    for (int i = tid; i < NA; i += 256) cs[i] = g_cs[i];
    __syncthreads();

    // 8x4 lane tile, 2x4 warp tiles -> 16x16 block tile
    int lane = tid & 31, w = tid >> 5;
    int x = ((int)blockIdx.x & 31) * 16 + (w & 1) * 8 + (lane & 7);
    int y = ((int)blockIdx.x >> 5) * 16 + (w >> 1) * 4 + (lane >> 3);
    float xc = (float)x - 256.0f;
    float yc = (float)y - 256.0f;

    float e0 = 0.f, e1 = 0.f;
    const float S = (float)(729.0 / (2.0 * PI_D));
    float rS = sqrtf(xc * xc + yc * yc) * S;
    const unsigned FULL = 0xffffffffu;

    if (__any_sync(FULL, rS < 1500.0f)) {
        exact_range(0, NA - 1, xc, yc, cs, e0, e1);
    } else {
        float phi = atan2f(yc, xc);
        float ts = phi + (float)(PI_D * 0.5);
        if (ts < 0.f) ts += PI_F;
        else if (ts >= PI_F) ts -= PI_F;
        // unwrap into lane0's frame (true spread < pi/2 at rS >= 1500)
        float ref = __shfl_sync(FULL, ts, 0);
        float d = ts - ref;
        if (d > (float)(PI_D * 0.5)) ts -= PI_F;
        else if (d < (float)(-PI_D * 0.5)) ts += PI_F;

        float delta = fmaf(728.5f / rS, 1.05f, 0.004f);
        const float inv_step = (float)(179.0 / PI_D);
        int aL = (int)floorf((ts - delta) * inv_step);
        int aH = (int)ceilf((ts + delta) * inv_step);
        aL = __reduce_min_sync(FULL, aL);
        aH = __reduce_max_sync(FULL, aH);
        // normalize so window overlaps [0,179]
        if (aH < 0)        { aL += NA - 1; aH += NA - 1; }
        else if (aL > NA - 1) { aL -= NA - 1; aH -= NA - 1; }

        if (aH - aL >= NA - 2) {
            exact_range(0, NA - 1, xc, yc, cs, e0, e1);
        } else if (aL >= 0 && aH <= NA - 1) {
            exact_range(aL, aH, xc, yc, cs, e0, e1);
            if (aL > 0)      clip_range(0, aL - 1, 0, xc, yc, cs, e0, e1);
            if (aH < NA - 1) clip_range(aH + 1, NA - 1, NA - 1, xc, yc, cs, e0, e1);
        } else if (aL < 0) {
            // windows [0,aH] and [aL+179,179]; complement [aH+1, aL+178]
            int lo = aH + 1, hi = aL + NA - 2;
            exact_range(0, aH, xc, yc, cs, e0, e1);
            exact_range(aL + NA - 1, NA - 1, xc, yc, cs, e0, e1);
            clip_range(lo, hi, (lo + hi) >> 1, xc, yc, cs, e0, e1);
        } else {
            // aH > 179: windows [0,aH-179] and [aL,179]; complement between
            int lo = aH - NA + 2, hi = aL - 1;
            exact_range(0, aH - NA + 1, xc, yc, cs, e0, e1);
            exact_range(aL, NA - 1, xc, yc, cs, e0, e1);
            clip_range(lo, hi, (lo + hi) >> 1, xc, yc, cs, e0, e1);
        }
    }

    const float scale = (float)(PI_D / (double)NA);
    int p = y * NW + x;
    out[p] = fmaxf(e0 * scale, 0.f);
    out[NH * NW + p] = fmaxf(e1 * scale, 0.f);
}

// ---------------------------------------------------------------------------
extern "C" void kernel_launch(void* const* d_in, const int* in_sizes, int n_in,
                              void* d_out, int out_size) {
    const float* sino = (const float*)d_in[0];
    float* out = (float*)d_out;

    k_filter<<<NB * NA, 128>>>(sino);
    k_edge<<<1, 32>>>();
    k_backproj<<<1024, 256>>>(out);
}

// round 10
// speedup vs baseline: 1.4505x; 1.4505x over previous
#include <cuda_runtime.h>
#include <cstdint>

#define ND 729
#define NA 180
#define NB 2
#define NH 512
#define NW 512
#define PI_D 3.141592653589793

// Scratch (no cudaMalloc allowed)
__device__ float2 g_filt2[NA * ND];    // batch-interleaved: [a][d] -> (b0, b1)
__device__ float2 g_cs[NA];            // (cos*S, sin*S), S = 729/(2*pi)
__device__ float4 g_edge[NA];          // {f0_b0, f728_b0, f0_b1, f728_b1}

// ---------------------------------------------------------------------------
// Kernel 1: filter via closed-form piecewise-linear conv kernel
//   h(d) = (1/729)*(1/8 + min(d,729-d)/1458)
// prefix sums P,Q over the single row; doubled-array prefixes reconstructed:
//   j<=729: P2=P[j], Q2=Q[j];  j>729: P2=T+P[j-729], Q2=Q729+Q[j-729]+729*P[j-729]
// out[n] = c0*T + c1*W[n],
//   W[n] = (n+729)(P2[n+730]-P2[n+365]) - (Q2[n+730]-Q2[n+365])
//        + (Q2[n+365]-Q2[n+1]) - n(P2[n+365]-P2[n+1])
// 256 threads/row (3 elems each) for a short latency chain.
// ---------------------------------------------------------------------------
__global__ void __launch_bounds__(256) k_filter(const float* __restrict__ sino) {
    __shared__ float  s_sh[768];
    __shared__ float2 pq[730];
    __shared__ float2 wsum[8];

    int tid = threadIdx.x, lane = tid & 31, wid = tid >> 5;
    int row = blockIdx.x;
    int b = (row >= NA) ? 1 : 0;
    int a = row - b * NA;
    const float* src = sino + row * ND;

    for (int i = tid; i < 768; i += 256) s_sh[i] = (i < ND) ? __ldg(src + i) : 0.f;
    __syncthreads();

    int j0 = tid * 3;
    float2 loc[3];
    float p = 0.f, q = 0.f;
    #pragma unroll
    for (int k = 0; k < 3; k++) {
        int j = j0 + k;
        float v = (j < 768) ? s_sh[j] : 0.f;
        p += v;
        q = fmaf((float)j, v, q);
        loc[k] = make_float2(p, q);
    }
    float tp = p, tq = q;

    #pragma unroll
    for (int o = 1; o < 32; o <<= 1) {
        float ax = __shfl_up_sync(0xffffffffu, p, o);
        float aq = __shfl_up_sync(0xffffffffu, q, o);
        if (lane >= o) { p += ax; q += aq; }
    }
    if (lane == 31) wsum[wid] = make_float2(p, q);
    __syncthreads();

    float wx = 0.f, wq = 0.f;
    #pragma unroll
    for (int w = 0; w < 8; w++)
        if (w < wid) { wx += wsum[w].x; wq += wsum[w].y; }
    float ex = wx + p - tp, eq = wq + q - tq;

    if (tid == 0) pq[0] = make_float2(0.f, 0.f);
    #pragma unroll
    for (int k = 0; k < 3; k++) {
        int j = j0 + k;
        if (j < ND) pq[j + 1] = make_float2(ex + loc[k].x, eq + loc[k].y);
    }
    __syncthreads();

    float T = pq[ND].x, Q9 = pq[ND].y;
    const float c0T = T * (1.0f / 5832.0f);
    const float c1  = 1.0f / 1062882.0f;

    float* fdst = (float*)g_filt2;
    for (int n = tid; n < ND; n += 256) {
        float2 A = pq[n + 1];
        float2 B;
        if (n + 365 <= ND) B = pq[n + 365];
        else { float2 r = pq[n + 365 - ND]; B = make_float2(T + r.x, Q9 + r.y + 729.f * r.x); }
        float2 C;
        { float2 r = pq[n + 1]; C = make_float2(T + r.x, Q9 + r.y + 729.f * r.x); }
        float W = (float)(n + 729) * (C.x - B.x) - (C.y - B.y)
                + (B.y - A.y) - (float)n * (B.x - A.x);
        float f = fmaf(c1, W, c0T);
        fdst[(a * ND + n) * 2 + b] = f;
        if (n == 0)   ((float*)(g_edge + a))[2 * b + 0] = f;
        if (n == 728) ((float*)(g_edge + a))[2 * b + 1] = f;
    }

    if (tid == 0 && b == 0) {
        double ang = (double)a * (PI_D / 179.0);
        double S = 729.0 / (2.0 * PI_D);
        g_cs[a] = make_float2((float)(cos(ang) * S), (float)(sin(ang) * S));
    }
}

// ---------------------------------------------------------------------------
// Kernel 2: base pass. For every pixel, base = sum_a (t(a)>0 ? f[a,728] : f[a,0])
// computed O(1): sign of t = sign of cos(theta_a - phi) has exactly one flip
// over the inclusive [0,pi] grid -> 8-step binary search with EXACT per-angle
// t evaluation, then two prefix-sum lookups. Writes RAW sums to out.
// ---------------------------------------------------------------------------
__global__ void __launch_bounds__(256) k_base(float* __restrict__ out) {
    __shared__ float2 cs[NA];
    __shared__ float4 pre[NA + 1];
    int tid = threadIdx.x;
    for (int i = tid; i < NA; i += 256) cs[i] = g_cs[i];
    if (tid < 32) {
        float4 acc = make_float4(0.f, 0.f, 0.f, 0.f);
        float4 loc[6];
        #pragma unroll
        for (int k = 0; k < 6; k++) {
            int a2 = tid * 6 + k;
            float4 v = (a2 < NA) ? __ldg(g_edge + a2) : make_float4(0.f, 0.f, 0.f, 0.f);
            acc.x += v.x; acc.y += v.y; acc.z += v.z; acc.w += v.w;
            loc[k] = acc;
        }
        float4 tot = acc;
        #pragma unroll
        for (int o = 1; o < 32; o <<= 1) {
            float ax = __shfl_up_sync(0xffffffffu, acc.x, o);
            float ay = __shfl_up_sync(0xffffffffu, acc.y, o);
            float az = __shfl_up_sync(0xffffffffu, acc.z, o);
            float aw = __shfl_up_sync(0xffffffffu, acc.w, o);
            if (tid >= o) { acc.x += ax; acc.y += ay; acc.z += az; acc.w += aw; }
        }
        float4 excl = make_float4(acc.x - tot.x, acc.y - tot.y, acc.z - tot.z, acc.w - tot.w);
        #pragma unroll
        for (int k = 0; k < 6; k++) {
            int a2 = tid * 6 + k;
            if (a2 < NA)
                pre[a2 + 1] = make_float4(excl.x + loc[k].x, excl.y + loc[k].y,
                                          excl.z + loc[k].z, excl.w + loc[k].w);
        }
        if (tid == 0) pre[0] = make_float4(0.f, 0.f, 0.f, 0.f);
    }
    __syncthreads();

    int gid = blockIdx.x * 256 + tid;     // 0..262143
    int x = gid & (NW - 1);
    int y = gid >> 9;
    float xc = (float)x - 256.0f;
    float yc = (float)y - 256.0f;

    bool s0 = fmaf(yc, cs[0].y, xc * cs[0].x) > 0.f;
    int lo = 0, hi = NA;                  // hi: first flipped index (sentinel NA)
    #pragma unroll
    for (int it = 0; it < 8; it++) {
        int mid = (lo + hi) >> 1;
        bool sm = (mid < NA) ? (fmaf(yc, cs[mid].y, xc * cs[mid].x) > 0.f) : !s0;
        if (sm == s0) lo = mid; else hi = mid;
    }
    float4 Pj = pre[hi], Pe = pre[NA];
    float b0, b1;
    if (s0) { b0 = Pj.y + (Pe.x - Pj.x); b1 = Pj.w + (Pe.z - Pj.z); }
    else    { b0 = Pj.x + (Pe.y - Pj.y); b1 = Pj.z + (Pe.w - Pj.w); }
    int p = y * NW + x;
    out[p] = b0;
    out[NH * NW + p] = b1;
}

// ---------------------------------------------------------------------------
// Kernel 3: strip pass (angle-major scatter). For each angle, only the band
// 0 < t < 728 (width 728/max(|cx|,|cy|) <= 8.9 pixels) needs correction:
//   corr = f[a,idx] - f[a,728]   (t>0 inside the band, matching base's sign)
// Warp = (angle, 32-chunk of major axis); lanes at equal depth k read nearly
// the same f element (broadcast). ~1.7M RED.F32 total.
// ---------------------------------------------------------------------------
__global__ void __launch_bounds__(256) k_strip(float* __restrict__ out) {
    int w = threadIdx.x >> 5, lane = threadIdx.x & 31;
    int g = blockIdx.x * 8 + w;           // 0..2879
    int a = g >> 4;
    int m = (g & 15) * 32 + lane;         // major coord 0..511

    float2 c2 = __ldg(&g_cs[a]);
    float4 e  = __ldg(&g_edge[a]);
    float cx = c2.x, cy = c2.y;
    bool ymin = fabsf(cy) >= fabsf(cx);   // minor axis = y if true
    float A = ymin ? cx : cy;             // major-coeff
    float Bc = ymin ? cy : cx;            // minor-coeff, |Bc| >= 82
    float mc = (float)m - 256.f;
    float tA = mc * A;
    float r0 = (0.f - tA) / Bc;
    float r1 = (728.f - tA) / Bc;
    int mn0 = (int)floorf(fminf(r0, r1)) + 256 - 1;
    int CNT = (int)(728.f / fabsf(Bc)) + 3;

    const float2* frow = (const float2*)g_filt2 + a * ND;
    for (int k = 0; k < CNT; k++) {
        int mn = mn0 + k;
        if ((unsigned)mn < (unsigned)NW) {
            float mnc = (float)mn - 256.f;
            float xcv = ymin ? mc : mnc;
            float ycv = ymin ? mnc : mc;
            float t = fmaf(ycv, cy, xcv * cx);   // identical expr to k_base
            if (t > 0.f && t < 728.f) {
                int idx = (int)t;
                float2 v = __ldg(frow + idx);
                float c0 = v.x - e.y;
                float c1 = v.y - e.w;
                int x = ymin ? m : mn;
                int y = ymin ? mn : m;
                int p = y * NW + x;
                atomicAdd(out + p, c0);
                atomicAdd(out + NH * NW + p, c1);
            }
        }
    }
}

// ---------------------------------------------------------------------------
// Kernel 4: scale + ReLU (clip(0, max) == relu since global max > 0).
// ---------------------------------------------------------------------------
__global__ void __launch_bounds__(256) k_final(float4* __restrict__ out) {
    int i = blockIdx.x * 256 + threadIdx.x;   // 131072 float4s
    const float sc = (float)(PI_D / (double)NA);
    float4 v = out[i];
    v.x = fmaxf(v.x * sc, 0.f);
    v.y = fmaxf(v.y * sc, 0.f);
    v.z = fmaxf(v.z * sc, 0.f);
    v.w = fmaxf(v.w * sc, 0.f);
    out[i] = v;
}

// ---------------------------------------------------------------------------
extern "C" void kernel_launch(void* const* d_in, const int* in_sizes, int n_in,
                              void* d_out, int out_size) {
    const float* sino = (const float*)d_in[0];
    float* out = (float*)d_out;

    k_filter<<<NB * NA, 256>>>(sino);
    k_base<<<(NH * NW) / 256, 256>>>(out);
    k_strip<<<360, 256>>>(out);
    k_final<<<(NB * NH * NW) / 4 / 256, 256>>>((float4*)out);
}